// round 6
// baseline (speedup 1.0000x reference)
#include <cuda_runtime.h>

#define N_NODES 50000
#define E_EDGES 800000
#define DIM     128
#define G_GRAPHS 128
#define C_CLASSES 10
#define BM 64                      // GEMM rows per block
#define SMP 132                    // padded smem row stride (floats)

// Scratch (device globals: no allocation allowed)
__device__ float g_bufA[N_NODES * DIM];
__device__ float g_bufB[N_NODES * DIM];
__device__ float g_rel [N_NODES * DIM];
__device__ float g_pool[G_GRAPHS * DIM];
__device__ float g_cnt [G_GRAPHS];

// ---------------------------------------------------------------------------
// GEMM: for a 64-row slab of A (N x 128):
//   blockIdx.y == 0:  g_rel[n,o]  = sum_k act(A[n,k]) * Wrel[o,k]
//   blockIdx.y == 1:  next[n,o]   = sum_k act(A[n,k]) * Wroot[o,k] + bias[o]
// act = relu if apply_relu else identity (ReLU of previous layer folded here).
// ---------------------------------------------------------------------------
__global__ __launch_bounds__(256, 2)
void gemm_kernel(const float* __restrict__ A,
                 const float* __restrict__ Wrel,
                 const float* __restrict__ Wroot,
                 const float* __restrict__ bias,
                 float* __restrict__ rel_out,
                 float* __restrict__ next_out,
                 int apply_relu)
{
    extern __shared__ float sm[];
    float* As = sm;                 // [BM][SMP]
    float* Ws = sm + BM * SMP;      // Wt[k][o] : [128][SMP]

    const int tid = threadIdx.x;
    const int m0  = blockIdx.x * BM;
    const int which = blockIdx.y;
    const float* W = which ? Wroot : Wrel;

    // --- load A slab (64 x 128) into As[r][k], relu folded ---
    {
        int r  = tid >> 2;              // 0..63
        int kb = (tid & 3) * 32;        // 0,32,64,96
        int row = m0 + r;
        if (row < N_NODES) {
            const float4* src = (const float4*)(A + (size_t)row * DIM + kb);
            float4* dst = (float4*)(As + r * SMP + kb);
            #pragma unroll
            for (int i = 0; i < 8; i++) {
                float4 v = src[i];
                if (apply_relu) {
                    v.x = fmaxf(v.x, 0.f); v.y = fmaxf(v.y, 0.f);
                    v.z = fmaxf(v.z, 0.f); v.w = fmaxf(v.w, 0.f);
                }
                dst[i] = v;
            }
        } else {
            float4 z = make_float4(0.f, 0.f, 0.f, 0.f);
            float4* dst = (float4*)(As + r * SMP + kb);
            #pragma unroll
            for (int i = 0; i < 8; i++) dst[i] = z;
        }
    }
    // --- load W (128 x 128) transposed into Ws[k][o] ---
    {
        int o  = tid >> 1;              // 0..127
        int kb = (tid & 1) * 64;        // 0,64
        const float4* src = (const float4*)(W + (size_t)o * DIM + kb);
        #pragma unroll
        for (int i = 0; i < 16; i++) {
            float4 v = src[i];
            int k = kb + i * 4;
            Ws[(k + 0) * SMP + o] = v.x;
            Ws[(k + 1) * SMP + o] = v.y;
            Ws[(k + 2) * SMP + o] = v.z;
            Ws[(k + 3) * SMP + o] = v.w;
        }
    }
    __syncthreads();

    const int tx = tid & 15;            // output-col group: cols tx*8 .. +7
    const int ty = tid >> 4;            // row group: rows ty*4 .. +3

    float acc[4][8];
    #pragma unroll
    for (int i = 0; i < 4; i++)
        #pragma unroll
        for (int j = 0; j < 8; j++) acc[i][j] = 0.f;

    #pragma unroll 4
    for (int k = 0; k < 128; k++) {
        float a0 = As[(ty * 4 + 0) * SMP + k];
        float a1 = As[(ty * 4 + 1) * SMP + k];
        float a2 = As[(ty * 4 + 2) * SMP + k];
        float a3 = As[(ty * 4 + 3) * SMP + k];
        float4 b0 = *(const float4*)(Ws + k * SMP + tx * 8);
        float4 b1 = *(const float4*)(Ws + k * SMP + tx * 8 + 4);
        float bv[8] = {b0.x, b0.y, b0.z, b0.w, b1.x, b1.y, b1.z, b1.w};
        #pragma unroll
        for (int j = 0; j < 8; j++) {
            acc[0][j] = fmaf(a0, bv[j], acc[0][j]);
            acc[1][j] = fmaf(a1, bv[j], acc[1][j]);
            acc[2][j] = fmaf(a2, bv[j], acc[2][j]);
            acc[3][j] = fmaf(a3, bv[j], acc[3][j]);
        }
    }

    float bconst[8];
    if (which) {
        #pragma unroll
        for (int j = 0; j < 8; j++) bconst[j] = bias[tx * 8 + j];
    }

    float* outp = which ? next_out : rel_out;
    #pragma unroll
    for (int i = 0; i < 4; i++) {
        int row = m0 + ty * 4 + i;
        if (row < N_NODES) {
            float4 v0, v1;
            if (which) {
                v0 = make_float4(acc[i][0] + bconst[0], acc[i][1] + bconst[1],
                                 acc[i][2] + bconst[2], acc[i][3] + bconst[3]);
                v1 = make_float4(acc[i][4] + bconst[4], acc[i][5] + bconst[5],
                                 acc[i][6] + bconst[6], acc[i][7] + bconst[7]);
            } else {
                v0 = make_float4(acc[i][0], acc[i][1], acc[i][2], acc[i][3]);
                v1 = make_float4(acc[i][4], acc[i][5], acc[i][6], acc[i][7]);
            }
            float4* dst = (float4*)(outp + (size_t)row * DIM + tx * 8);
            dst[0] = v0;
            dst[1] = v1;
        }
    }
}

// ---------------------------------------------------------------------------
// Scatter: one warp per edge. next[dst] += rel[src]  (128 floats per edge)
// edge_index is INT32 on device (JAX x64-disabled materializes int64 as int32).
// ---------------------------------------------------------------------------
__global__ __launch_bounds__(256)
void scatter_kernel(const int* __restrict__ ei,
                    const float* __restrict__ rel,
                    float* __restrict__ next)
{
    int gwarp = (blockIdx.x * blockDim.x + threadIdx.x) >> 5;
    int lane  = threadIdx.x & 31;
    if (gwarp >= E_EDGES) return;
    int s = ei[gwarp];
    int d = ei[E_EDGES + gwarp];
    float4 v = ((const float4*)(rel + (size_t)s * DIM))[lane];
    float* p = next + (size_t)d * DIM + lane * 4;
    atomicAdd(p + 0, v.x);
    atomicAdd(p + 1, v.y);
    atomicAdd(p + 2, v.z);
    atomicAdd(p + 3, v.w);
}

// ---------------------------------------------------------------------------
// Zero pool accumulators
// ---------------------------------------------------------------------------
__global__ void zero_kernel(float* __restrict__ pool, float* __restrict__ cnt)
{
    int i = blockIdx.x * blockDim.x + threadIdx.x;
    if (i < G_GRAPHS * DIM) pool[i] = 0.f;
    if (i < G_GRAPHS) cnt[i] = 0.f;
}

// ---------------------------------------------------------------------------
// Mean pool: batch (int32) is SORTED -> run-length accumulation. 128 threads
// per block (one per feature), 64 nodes per block. ReLU applied here.
// ---------------------------------------------------------------------------
__global__ __launch_bounds__(128)
void pool_kernel(const float* __restrict__ h,
                 const int* __restrict__ batch,
                 float* __restrict__ pool,
                 float* __restrict__ cnt)
{
    int f  = threadIdx.x;
    int n0 = blockIdx.x * 64;
    int n1 = n0 + 64;
    if (n1 > N_NODES) n1 = N_NODES;

    int cur = batch[n0];
    float acc = 0.f;
    for (int n = n0; n < n1; n++) {
        int b = batch[n];
        if (b != cur) {
            atomicAdd(&pool[cur * DIM + f], acc);
            acc = 0.f;
            cur = b;
        }
        acc += fmaxf(h[(size_t)n * DIM + f], 0.f);
    }
    atomicAdd(&pool[cur * DIM + f], acc);

    if (f == 0) {
        int c2 = batch[n0];
        float c = 0.f;
        for (int n = n0; n < n1; n++) {
            int b = batch[n];
            if (b != c2) { atomicAdd(&cnt[c2], c); c = 0.f; c2 = b; }
            c += 1.f;
        }
        atomicAdd(&cnt[c2], c);
    }
}

// ---------------------------------------------------------------------------
// Head: out[g,c] = (pool[g]/max(cnt,1)) . lin_w[c] + lin_b[c]
// ---------------------------------------------------------------------------
__global__ __launch_bounds__(128)
void final_kernel(const float* __restrict__ pool,
                  const float* __restrict__ cnt,
                  const float* __restrict__ lw,
                  const float* __restrict__ lb,
                  float* __restrict__ out)
{
    __shared__ float red[4];
    int g = blockIdx.x;
    int t = threadIdx.x;
    float c = fmaxf(cnt[g], 1.0f);
    float v = pool[g * DIM + t] / c;
    for (int cc = 0; cc < C_CLASSES; cc++) {
        float p = v * lw[cc * DIM + t];
        #pragma unroll
        for (int off = 16; off; off >>= 1)
            p += __shfl_down_sync(0xffffffffu, p, off);
        if ((t & 31) == 0) red[t >> 5] = p;
        __syncthreads();
        if (t == 0)
            out[g * C_CLASSES + cc] = red[0] + red[1] + red[2] + red[3] + lb[cc];
        __syncthreads();
    }
}

// ---------------------------------------------------------------------------
extern "C" void kernel_launch(void* const* d_in, const int* in_sizes, int n_in,
                              void* d_out, int out_size)
{
    const float* x     = (const float*)d_in[0];
    const int*   ei    = (const int*)d_in[1];      // int32 on device
    const int*   batch = (const int*)d_in[2];      // int32 on device
    const float* Wrel[4]  = {(const float*)d_in[3], (const float*)d_in[6],
                             (const float*)d_in[9], (const float*)d_in[12]};
    const float* brel[4]  = {(const float*)d_in[4], (const float*)d_in[7],
                             (const float*)d_in[10], (const float*)d_in[13]};
    const float* Wroot[4] = {(const float*)d_in[5], (const float*)d_in[8],
                             (const float*)d_in[11], (const float*)d_in[14]};
    const float* lin_w = (const float*)d_in[15];
    const float* lin_b = (const float*)d_in[16];
    float* out = (float*)d_out;

    float *bufA, *bufB, *rel, *pool, *cnt;
    cudaGetSymbolAddress((void**)&bufA, g_bufA);
    cudaGetSymbolAddress((void**)&bufB, g_bufB);
    cudaGetSymbolAddress((void**)&rel,  g_rel);
    cudaGetSymbolAddress((void**)&pool, g_pool);
    cudaGetSymbolAddress((void**)&cnt,  g_cnt);

    size_t smem = (size_t)(BM + 128) * SMP * sizeof(float);  // ~99 KB
    cudaFuncSetAttribute(gemm_kernel, cudaFuncAttributeMaxDynamicSharedMemorySize,
                         (int)smem);

    dim3 ggrid((N_NODES + BM - 1) / BM, 2);
    int  sblocks = (E_EDGES * 32) / 256;   // one warp per edge

    const float* h = x;
    for (int i = 0; i < 4; i++) {
        float* nxt = (i & 1) ? bufB : bufA;
        gemm_kernel<<<ggrid, 256, smem>>>(h, Wrel[i], Wroot[i], brel[i],
                                          rel, nxt, i > 0);
        scatter_kernel<<<sblocks, 256>>>(ei, rel, nxt);
        h = nxt;
    }

    zero_kernel<<<(G_GRAPHS * DIM + 255) / 256, 256>>>(pool, cnt);
    pool_kernel<<<(N_NODES + 63) / 64, 128>>>(h, batch, pool, cnt);
    final_kernel<<<G_GRAPHS, 128>>>(pool, cnt, lin_w, lin_b, out);
}

// round 7
// speedup vs baseline: 1.7685x; 1.7685x over previous
#include <cuda_runtime.h>

#define N_NODES 50000
#define E_EDGES 800000
#define DIM     128
#define G_GRAPHS 128
#define C_CLASSES 10
#define BM 64                      // GEMM rows per block
#define SMP 132                    // padded smem row stride (floats)

// Scratch (device globals: no allocation allowed)
__device__ float g_bufA[N_NODES * DIM];
__device__ float g_bufB[N_NODES * DIM];
__device__ float g_rel [N_NODES * DIM];
__device__ float g_pool[G_GRAPHS * DIM];
__device__ float g_cnt [G_GRAPHS];
// CSR scratch (built once per launch; edge_index constant across layers)
__device__ int g_deg   [N_NODES];
__device__ int g_rowptr[N_NODES + 1];
__device__ int g_cursor[N_NODES];
__device__ int g_csrc  [E_EDGES];

// ---------------------------------------------------------------------------
// GEMM: for a 64-row slab of A (N x 128):
//   blockIdx.y == 0:  g_rel[n,o]  = sum_k act(A[n,k]) * Wrel[o,k]
//   blockIdx.y == 1:  next[n,o]   = sum_k act(A[n,k]) * Wroot[o,k] + bias[o]
// act = relu if apply_relu else identity (ReLU of previous layer folded here).
// ---------------------------------------------------------------------------
__global__ __launch_bounds__(256, 2)
void gemm_kernel(const float* __restrict__ A,
                 const float* __restrict__ Wrel,
                 const float* __restrict__ Wroot,
                 const float* __restrict__ bias,
                 float* __restrict__ rel_out,
                 float* __restrict__ next_out,
                 int apply_relu)
{
    extern __shared__ float sm[];
    float* As = sm;                 // [BM][SMP]
    float* Ws = sm + BM * SMP;      // Wt[k][o] : [128][SMP]

    const int tid = threadIdx.x;
    const int m0  = blockIdx.x * BM;
    const int which = blockIdx.y;
    const float* W = which ? Wroot : Wrel;

    // --- load A slab (64 x 128) into As[r][k], relu folded ---
    {
        int r  = tid >> 2;              // 0..63
        int kb = (tid & 3) * 32;        // 0,32,64,96
        int row = m0 + r;
        if (row < N_NODES) {
            const float4* src = (const float4*)(A + (size_t)row * DIM + kb);
            float4* dst = (float4*)(As + r * SMP + kb);
            #pragma unroll
            for (int i = 0; i < 8; i++) {
                float4 v = src[i];
                if (apply_relu) {
                    v.x = fmaxf(v.x, 0.f); v.y = fmaxf(v.y, 0.f);
                    v.z = fmaxf(v.z, 0.f); v.w = fmaxf(v.w, 0.f);
                }
                dst[i] = v;
            }
        } else {
            float4 z = make_float4(0.f, 0.f, 0.f, 0.f);
            float4* dst = (float4*)(As + r * SMP + kb);
            #pragma unroll
            for (int i = 0; i < 8; i++) dst[i] = z;
        }
    }
    // --- load W (128 x 128) transposed into Ws[k][o] ---
    {
        int o  = tid >> 1;              // 0..127
        int kb = (tid & 1) * 64;        // 0,64
        const float4* src = (const float4*)(W + (size_t)o * DIM + kb);
        #pragma unroll
        for (int i = 0; i < 16; i++) {
            float4 v = src[i];
            int k = kb + i * 4;
            Ws[(k + 0) * SMP + o] = v.x;
            Ws[(k + 1) * SMP + o] = v.y;
            Ws[(k + 2) * SMP + o] = v.z;
            Ws[(k + 3) * SMP + o] = v.w;
        }
    }
    __syncthreads();

    const int tx = tid & 15;            // output-col group: cols tx*8 .. +7
    const int ty = tid >> 4;            // row group: rows ty*4 .. +3

    float acc[4][8];
    #pragma unroll
    for (int i = 0; i < 4; i++)
        #pragma unroll
        for (int j = 0; j < 8; j++) acc[i][j] = 0.f;

    #pragma unroll 4
    for (int k = 0; k < 128; k++) {
        float a0 = As[(ty * 4 + 0) * SMP + k];
        float a1 = As[(ty * 4 + 1) * SMP + k];
        float a2 = As[(ty * 4 + 2) * SMP + k];
        float a3 = As[(ty * 4 + 3) * SMP + k];
        float4 b0 = *(const float4*)(Ws + k * SMP + tx * 8);
        float4 b1 = *(const float4*)(Ws + k * SMP + tx * 8 + 4);
        float bv[8] = {b0.x, b0.y, b0.z, b0.w, b1.x, b1.y, b1.z, b1.w};
        #pragma unroll
        for (int j = 0; j < 8; j++) {
            acc[0][j] = fmaf(a0, bv[j], acc[0][j]);
            acc[1][j] = fmaf(a1, bv[j], acc[1][j]);
            acc[2][j] = fmaf(a2, bv[j], acc[2][j]);
            acc[3][j] = fmaf(a3, bv[j], acc[3][j]);
        }
    }

    float bconst[8];
    if (which) {
        #pragma unroll
        for (int j = 0; j < 8; j++) bconst[j] = bias[tx * 8 + j];
    }

    float* outp = which ? next_out : rel_out;
    #pragma unroll
    for (int i = 0; i < 4; i++) {
        int row = m0 + ty * 4 + i;
        if (row < N_NODES) {
            float4 v0, v1;
            if (which) {
                v0 = make_float4(acc[i][0] + bconst[0], acc[i][1] + bconst[1],
                                 acc[i][2] + bconst[2], acc[i][3] + bconst[3]);
                v1 = make_float4(acc[i][4] + bconst[4], acc[i][5] + bconst[5],
                                 acc[i][6] + bconst[6], acc[i][7] + bconst[7]);
            } else {
                v0 = make_float4(acc[i][0], acc[i][1], acc[i][2], acc[i][3]);
                v1 = make_float4(acc[i][4], acc[i][5], acc[i][6], acc[i][7]);
            }
            float4* dst = (float4*)(outp + (size_t)row * DIM + tx * 8);
            dst[0] = v0;
            dst[1] = v1;
        }
    }
}

// ---------------------------------------------------------------------------
// CSR build (once per launch): deg histogram -> exclusive scan -> fill
// ---------------------------------------------------------------------------
__global__ void deg_zero_kernel()
{
    int i = blockIdx.x * blockDim.x + threadIdx.x;
    if (i < N_NODES) g_deg[i] = 0;
}

__global__ void deg_hist_kernel(const int* __restrict__ ei)
{
    int e = blockIdx.x * blockDim.x + threadIdx.x;
    if (e < E_EDGES) atomicAdd(&g_deg[ei[E_EDGES + e]], 1);
}

// Single-block exclusive scan over g_deg -> g_rowptr (+ cursor copy).
__global__ __launch_bounds__(1024)
void scan_kernel()
{
    __shared__ int sh[1024];
    __shared__ int carry;
    if (threadIdx.x == 0) carry = 0;
    __syncthreads();
    for (int base = 0; base < N_NODES; base += 1024) {
        int i = base + threadIdx.x;
        int v = (i < N_NODES) ? g_deg[i] : 0;
        sh[threadIdx.x] = v;
        __syncthreads();
        #pragma unroll
        for (int off = 1; off < 1024; off <<= 1) {
            int t = (threadIdx.x >= off) ? sh[threadIdx.x - off] : 0;
            __syncthreads();
            sh[threadIdx.x] += t;
            __syncthreads();
        }
        int excl = sh[threadIdx.x] - v;
        int c = carry;
        if (i < N_NODES) {
            g_rowptr[i] = c + excl;
            g_cursor[i] = c + excl;
        }
        int total = sh[1023];
        __syncthreads();
        if (threadIdx.x == 0) carry = c + total;
        __syncthreads();
    }
    if (threadIdx.x == 0) g_rowptr[N_NODES] = carry;
}

__global__ void fill_kernel(const int* __restrict__ ei)
{
    int e = blockIdx.x * blockDim.x + threadIdx.x;
    if (e < E_EDGES) {
        int d = ei[E_EDGES + e];
        int pos = atomicAdd(&g_cursor[d], 1);
        g_csrc[pos] = ei[e];
    }
}

// ---------------------------------------------------------------------------
// Gather: one warp per dst node. next[d] += sum_{s in in(d)} rel[s].
// Atomic-free: each warp exclusively owns its 512B output row.
// ---------------------------------------------------------------------------
__global__ __launch_bounds__(256)
void gather_kernel(const float* __restrict__ rel,
                   float* __restrict__ next)
{
    int w    = (blockIdx.x * blockDim.x + threadIdx.x) >> 5;
    int lane = threadIdx.x & 31;
    if (w >= N_NODES) return;
    int beg = g_rowptr[w];
    int end = g_rowptr[w + 1];

    float4 acc = make_float4(0.f, 0.f, 0.f, 0.f);
    int i = beg;
    // 4-way batched loads for MLP
    for (; i + 4 <= end; i += 4) {
        int s0 = g_csrc[i + 0];
        int s1 = g_csrc[i + 1];
        int s2 = g_csrc[i + 2];
        int s3 = g_csrc[i + 3];
        float4 v0 = ((const float4*)(rel + (size_t)s0 * DIM))[lane];
        float4 v1 = ((const float4*)(rel + (size_t)s1 * DIM))[lane];
        float4 v2 = ((const float4*)(rel + (size_t)s2 * DIM))[lane];
        float4 v3 = ((const float4*)(rel + (size_t)s3 * DIM))[lane];
        acc.x += v0.x + v1.x + v2.x + v3.x;
        acc.y += v0.y + v1.y + v2.y + v3.y;
        acc.z += v0.z + v1.z + v2.z + v3.z;
        acc.w += v0.w + v1.w + v2.w + v3.w;
    }
    for (; i < end; i++) {
        int s = g_csrc[i];
        float4 v = ((const float4*)(rel + (size_t)s * DIM))[lane];
        acc.x += v.x; acc.y += v.y; acc.z += v.z; acc.w += v.w;
    }

    float4* p = (float4*)(next + (size_t)w * DIM) + lane;
    float4 o = *p;
    o.x += acc.x; o.y += acc.y; o.z += acc.z; o.w += acc.w;
    *p = o;
}

// ---------------------------------------------------------------------------
// Zero pool accumulators
// ---------------------------------------------------------------------------
__global__ void zero_kernel(float* __restrict__ pool, float* __restrict__ cnt)
{
    int i = blockIdx.x * blockDim.x + threadIdx.x;
    if (i < G_GRAPHS * DIM) pool[i] = 0.f;
    if (i < G_GRAPHS) cnt[i] = 0.f;
}

// ---------------------------------------------------------------------------
// Mean pool: batch (int32) is SORTED -> run-length accumulation. 128 threads
// per block (one per feature), 64 nodes per block. ReLU applied here.
// ---------------------------------------------------------------------------
__global__ __launch_bounds__(128)
void pool_kernel(const float* __restrict__ h,
                 const int* __restrict__ batch,
                 float* __restrict__ pool,
                 float* __restrict__ cnt)
{
    int f  = threadIdx.x;
    int n0 = blockIdx.x * 64;
    int n1 = n0 + 64;
    if (n1 > N_NODES) n1 = N_NODES;

    int cur = batch[n0];
    float acc = 0.f;
    for (int n = n0; n < n1; n++) {
        int b = batch[n];
        if (b != cur) {
            atomicAdd(&pool[cur * DIM + f], acc);
            acc = 0.f;
            cur = b;
        }
        acc += fmaxf(h[(size_t)n * DIM + f], 0.f);
    }
    atomicAdd(&pool[cur * DIM + f], acc);

    if (f == 0) {
        int c2 = batch[n0];
        float c = 0.f;
        for (int n = n0; n < n1; n++) {
            int b = batch[n];
            if (b != c2) { atomicAdd(&cnt[c2], c); c = 0.f; c2 = b; }
            c += 1.f;
        }
        atomicAdd(&cnt[c2], c);
    }
}

// ---------------------------------------------------------------------------
// Head: out[g,c] = (pool[g]/max(cnt,1)) . lin_w[c] + lin_b[c]
// ---------------------------------------------------------------------------
__global__ __launch_bounds__(128)
void final_kernel(const float* __restrict__ pool,
                  const float* __restrict__ cnt,
                  const float* __restrict__ lw,
                  const float* __restrict__ lb,
                  float* __restrict__ out)
{
    __shared__ float red[4];
    int g = blockIdx.x;
    int t = threadIdx.x;
    float c = fmaxf(cnt[g], 1.0f);
    float v = pool[g * DIM + t] / c;
    for (int cc = 0; cc < C_CLASSES; cc++) {
        float p = v * lw[cc * DIM + t];
        #pragma unroll
        for (int off = 16; off; off >>= 1)
            p += __shfl_down_sync(0xffffffffu, p, off);
        if ((t & 31) == 0) red[t >> 5] = p;
        __syncthreads();
        if (t == 0)
            out[g * C_CLASSES + cc] = red[0] + red[1] + red[2] + red[3] + lb[cc];
        __syncthreads();
    }
}

// ---------------------------------------------------------------------------
extern "C" void kernel_launch(void* const* d_in, const int* in_sizes, int n_in,
                              void* d_out, int out_size)
{
    const float* x     = (const float*)d_in[0];
    const int*   ei    = (const int*)d_in[1];      // int32 on device
    const int*   batch = (const int*)d_in[2];      // int32 on device
    const float* Wrel[4]  = {(const float*)d_in[3], (const float*)d_in[6],
                             (const float*)d_in[9], (const float*)d_in[12]};
    const float* brel[4]  = {(const float*)d_in[4], (const float*)d_in[7],
                             (const float*)d_in[10], (const float*)d_in[13]};
    const float* Wroot[4] = {(const float*)d_in[5], (const float*)d_in[8],
                             (const float*)d_in[11], (const float*)d_in[14]};
    const float* lin_w = (const float*)d_in[15];
    const float* lin_b = (const float*)d_in[16];
    float* out = (float*)d_out;

    float *bufA, *bufB, *rel, *pool, *cnt;
    cudaGetSymbolAddress((void**)&bufA, g_bufA);
    cudaGetSymbolAddress((void**)&bufB, g_bufB);
    cudaGetSymbolAddress((void**)&rel,  g_rel);
    cudaGetSymbolAddress((void**)&pool, g_pool);
    cudaGetSymbolAddress((void**)&cnt,  g_cnt);

    size_t smem = (size_t)(BM + 128) * SMP * sizeof(float);  // ~99 KB
    cudaFuncSetAttribute(gemm_kernel, cudaFuncAttributeMaxDynamicSharedMemorySize,
                         (int)smem);

    // --- Build CSR once (edge_index identical for all layers) ---
    deg_zero_kernel<<<(N_NODES + 255) / 256, 256>>>();
    deg_hist_kernel<<<(E_EDGES + 255) / 256, 256>>>(ei);
    scan_kernel<<<1, 1024>>>();
    fill_kernel<<<(E_EDGES + 255) / 256, 256>>>(ei);

    dim3 ggrid((N_NODES + BM - 1) / BM, 2);
    int  gthblocks = (N_NODES * 32 + 255) / 256;   // one warp per dst node

    const float* h = x;
    for (int i = 0; i < 4; i++) {
        float* nxt = (i & 1) ? bufB : bufA;
        gemm_kernel<<<ggrid, 256, smem>>>(h, Wrel[i], Wroot[i], brel[i],
                                          rel, nxt, i > 0);
        gather_kernel<<<gthblocks, 256>>>(rel, nxt);
        h = nxt;
    }

    zero_kernel<<<(G_GRAPHS * DIM + 255) / 256, 256>>>(pool, cnt);
    pool_kernel<<<(N_NODES + 63) / 64, 128>>>(h, batch, pool, cnt);
    final_kernel<<<G_GRAPHS, 128>>>(pool, cnt, lin_w, lin_b, out);
}